// round 15
// baseline (speedup 1.0000x reference)
#include <cuda_runtime.h>
#include <math.h>

#define Tdim 1024
#define BT   2048   // B*T
#define DM   1024
#define NH   16
#define HD   64
#define KVL  512
#define NE   4
#define DH   4096

// ---------------- scratch (device globals; no runtime allocation) ----------------
__device__ float g_xn  [BT*DM];
__device__ float g_q   [BT*DM];
__device__ float g_lat [BT*KVL];
__device__ float g_k   [BT*DM];
__device__ float g_v   [BT*DM];
__device__ float g_attn[BT*DM];
__device__ float g_x1  [BT*DM];
__device__ float g_xn2 [BT*DM];
__device__ float g_h   [BT*DH];
__device__ int   g_cnt [NE];
__device__ int   g_idx [NE*BT];
// tf32-rounded small weights (14MB total; W1/W2 intentionally NOT copied)
__device__ float g_wq  [DM*DM];
__device__ float g_wdkv[KVL*DM];
__device__ float g_wuk [DM*KVL];
__device__ float g_wuv [DM*KVL];
__device__ float g_wo  [DM*DM];

// ---------------- helpers ----------------
__device__ __forceinline__ unsigned f2tf(float x) {
    unsigned r; asm("cvt.rna.tf32.f32 %0, %1;" : "=r"(r) : "f"(x)); return r;
}
__device__ __forceinline__ float tfr(float x) { return __uint_as_float(f2tf(x)); }
__device__ __forceinline__ void mma_tf32(float* c, const unsigned* a, unsigned b0, unsigned b1) {
    asm volatile(
        "mma.sync.aligned.m16n8k8.row.col.f32.tf32.tf32.f32 "
        "{%0,%1,%2,%3}, {%4,%5,%6,%7}, {%8,%9}, {%0,%1,%2,%3};"
        : "+f"(c[0]), "+f"(c[1]), "+f"(c[2]), "+f"(c[3])
        : "r"(a[0]), "r"(a[1]), "r"(a[2]), "r"(a[3]), "r"(b0), "r"(b1));
}
__device__ __forceinline__ void cp_async16(unsigned dst, const void* src, int srcbytes) {
    asm volatile("cp.async.cg.shared.global [%0], [%1], 16, %2;"
                 :: "r"(dst), "l"(src), "r"(srcbytes));
}
__device__ __forceinline__ void cp_commit() { asm volatile("cp.async.commit_group;"); }
__device__ __forceinline__ void cp_wait0()  { asm volatile("cp.async.wait_group 0;"); }

// ---------------- fused small-weight pre-rounding (one launch) ----------------
#define NWQ   (DM*DM)
#define NWDKV (KVL*DM)
#define NWUK  (DM*KVL)
#define NWUV  (DM*KVL)
#define NWO   (DM*DM)
#define NW_TOTAL (NWQ + NWDKV + NWUK + NWUV + NWO)

__global__ __launch_bounds__(256) void cvtw5_kernel(
    const float* __restrict__ wq, const float* __restrict__ wdkv,
    const float* __restrict__ wuk, const float* __restrict__ wuv,
    const float* __restrict__ wo) {
    int i = blockIdx.x * 256 + threadIdx.x;
    if (i >= NW_TOTAL) return;
    if (i < NWQ) { g_wq[i] = tfr(wq[i]); return; }
    i -= NWQ;
    if (i < NWDKV) { g_wdkv[i] = tfr(wdkv[i]); return; }
    i -= NWDKV;
    if (i < NWUK) { g_wuk[i] = tfr(wuk[i]); return; }
    i -= NWUK;
    if (i < NWUV) { g_wuv[i] = tfr(wuv[i]); return; }
    i -= NWUV;
    g_wo[i] = tfr(wo[i]);
}

// ---------------- elementwise (producers emit RNA-tf32-rounded activations) ------
__global__ __launch_bounds__(256) void rmsnorm_kernel(
    const float* __restrict__ x, const float* __restrict__ w, float* __restrict__ out) {
    int row = blockIdx.x, tid = threadIdx.x;
    const float* xr = x + (long)row * DM;
    float ss = 0.f;
    for (int d = tid; d < DM; d += 256) { float v = xr[d]; ss += v * v; }
    __shared__ float red[256];
    red[tid] = ss; __syncthreads();
    for (int s = 128; s > 0; s >>= 1) { if (tid < s) red[tid] += red[tid + s]; __syncthreads(); }
    float scale = rsqrtf(red[0] / DM + 1e-6f);
    for (int d = tid; d < DM; d += 256) out[(long)row * DM + d] = tfr(w[d] * xr[d] * scale);
}

__global__ __launch_bounds__(256) void layernorm_kernel(
    float* __restrict__ p, const float* __restrict__ g, const float* __restrict__ b) {
    int row = blockIdx.x, tid = threadIdx.x;
    float* xr = p + (long)row * KVL;
    __shared__ float red[256];
    float s = 0.f;
    for (int d = tid; d < KVL; d += 256) s += xr[d];
    red[tid] = s; __syncthreads();
    for (int k = 128; k > 0; k >>= 1) { if (tid < k) red[tid] += red[tid + k]; __syncthreads(); }
    float mu = red[0] / KVL;
    __syncthreads();
    float vs = 0.f;
    for (int d = tid; d < KVL; d += 256) { float dv = xr[d] - mu; vs += dv * dv; }
    red[tid] = vs; __syncthreads();
    for (int k = 128; k > 0; k >>= 1) { if (tid < k) red[tid] += red[tid + k]; __syncthreads(); }
    float inv = rsqrtf(red[0] / KVL + 1e-5f);
    for (int d = tid; d < KVL; d += 256) xr[d] = tfr((xr[d] - mu) * inv * g[d] + b[d]);
}

// one launch, grid.y: 0 -> q, 1 -> k
__global__ __launch_bounds__(256) void rope_kernel(float* __restrict__ q, float* __restrict__ k) {
    float* p = blockIdx.y ? k : q;
    int id = blockIdx.x * 256 + threadIdx.x;
    int row = id >> 9;
    int rem = id & 511;
    int h = rem >> 5, d = rem & 31;
    int t = row & (Tdim - 1);
    float* base = p + (long)row * DM + h * HD + d;
    float x1 = base[0], x2 = base[32];
    float inv = powf(10000.f, -(float)d / 32.f);
    float ang = (float)t * inv;
    float sn = sinf(ang), cs = cosf(ang);
    base[0]  = tfr(x1 * cs - x2 * sn);
    base[32] = tfr(x1 * sn + x2 * cs);
}

__global__ void zero_cnt_kernel() { if (threadIdx.x < NE) g_cnt[threadIdx.x] = 0; }

__global__ __launch_bounds__(128) void gate_kernel(
    const float* __restrict__ xn2, const float* __restrict__ gw, const float* __restrict__ gb) {
    int row = blockIdx.x, tid = threadIdx.x;
    const float* xr = xn2 + (long)row * DM;
    float a0 = 0.f, a1 = 0.f, a2 = 0.f, a3 = 0.f;
    for (int d = tid; d < DM; d += 128) {
        float xv = xr[d];
        a0 += xv * gw[d]; a1 += xv * gw[DM + d]; a2 += xv * gw[2 * DM + d]; a3 += xv * gw[3 * DM + d];
    }
    __shared__ float red[4][128];
    red[0][tid] = a0; red[1][tid] = a1; red[2][tid] = a2; red[3][tid] = a3;
    __syncthreads();
    for (int s = 64; s > 0; s >>= 1) {
        if (tid < s) { for (int e = 0; e < 4; e++) red[e][tid] += red[e][tid + s]; }
        __syncthreads();
    }
    if (tid == 0) {
        float l0 = red[0][0] + gb[0], l1 = red[1][0] + gb[1];
        float l2 = red[2][0] + gb[2], l3 = red[3][0] + gb[3];
        int best = 0; float bv = l0;
        if (l1 > bv) { bv = l1; best = 1; }
        if (l2 > bv) { bv = l2; best = 2; }
        if (l3 > bv) { bv = l3; best = 3; }
        int pos = atomicAdd(&g_cnt[best], 1);
        g_idx[best * BT + pos] = row;
    }
}

// ---------------- tf32 mma GEMM, cp.async double-buffered, 512 threads, GBK=64 ---
// C[M,N] = A[M,K] * B[N,K]^T. Block 128x128x64, 16 warps (4x4), warp tile 32x32.
// Longer compute phase per slab fully hides the prefetch latency behind wait0.
#define GBM 128
#define GBN 128
#define GBK 64
#define GLD 68
#define GEMM_SMEM (4 * 128 * GLD * 4)   // 2 stages x (As+Bs)[128][68] = 139264 B

__global__ __launch_bounds__(512) void gemm_tf32(
    const float* __restrict__ A, const float* __restrict__ Bw, float* __restrict__ C,
    int M, int N, int K,
    const float* __restrict__ bias, const float* __restrict__ res,
    int relu, int use_idx, long wstride, int bcvt, int cvt_out) {
    extern __shared__ float sm[];
    unsigned sbase = (unsigned)__cvta_generic_to_shared(sm);

    int e = blockIdx.z;
    const float* Bm = Bw + (long)e * wstride;
    int Mz = M;
    const int* rowmap = nullptr;
    if (use_idx) { Mz = g_cnt[e]; rowmap = g_idx + e * BT; }
    int i0 = blockIdx.y * GBM;
    if (i0 >= Mz) return;
    int j0 = blockIdx.x * GBN;

    int tid = threadIdx.x;
    int warp = tid >> 5, lane = tid & 31;
    int wm = warp >> 2, wn = warp & 3;     // 4x4 warps, 32x32 warp tiles
    int lg = lane >> 2, lr = lane & 3;

    // gathered A rows for the 4 A-load slices (2048 float4 tasks / 512 threads)
    int arows[4]; int asz[4];
#pragma unroll
    for (int it = 0; it < 4; it++) {
        int r = (tid + it * 512) >> 4;      // 16 float4 per row (64 floats)
        int pos = i0 + r;
        bool v = pos < Mz;
        asz[it] = v ? 16 : 0;
        arows[it] = rowmap ? (v ? rowmap[pos] : 0) : pos;
    }

    float acc[2][4][4];
#pragma unroll
    for (int mi = 0; mi < 2; mi++)
#pragma unroll
        for (int ni = 0; ni < 4; ni++)
#pragma unroll
            for (int q = 0; q < 4; q++) acc[mi][ni][q] = 0.f;

    int KT = K / GBK;

    {
        unsigned adst = sbase;
        unsigned bdst = sbase + 128 * GLD * 4;
#pragma unroll
        for (int it = 0; it < 4; it++) {
            int f = tid + it * 512;
            int r = f >> 4, c4 = f & 15;
            cp_async16(adst + (r * GLD + c4 * 4) * 4, A + (long)arows[it] * K + c4 * 4, asz[it]);
            cp_async16(bdst + (r * GLD + c4 * 4) * 4, Bm + (long)(j0 + r) * K + c4 * 4, 16);
        }
        cp_commit();
    }

    for (int kt = 0; kt < KT; kt++) {
        cp_wait0();
        __syncthreads();
        if (kt + 1 < KT) {
            int nb = (kt + 1) & 1;
            int k0 = (kt + 1) * GBK;
            unsigned adst = sbase + (nb * 2) * 128 * GLD * 4;
            unsigned bdst = sbase + (nb * 2 + 1) * 128 * GLD * 4;
#pragma unroll
            for (int it = 0; it < 4; it++) {
                int f = tid + it * 512;
                int r = f >> 4, c4 = f & 15;
                cp_async16(adst + (r * GLD + c4 * 4) * 4, A + (long)arows[it] * K + k0 + c4 * 4, asz[it]);
                cp_async16(bdst + (r * GLD + c4 * 4) * 4, Bm + (long)(j0 + r) * K + k0 + c4 * 4, 16);
            }
            cp_commit();
        }
        const float* Asb = sm + (kt & 1) * 2 * 128 * GLD;
        const float* Bsb = Asb + 128 * GLD;
#pragma unroll
        for (int kk = 0; kk < 8; kk++) {
            unsigned af[2][4], bf[4][2];
#pragma unroll
            for (int mi = 0; mi < 2; mi++) {
                int r0 = wm * 32 + mi * 16 + lg;
                af[mi][0] = __float_as_uint(Asb[r0 * GLD + kk * 8 + lr]);
                af[mi][1] = __float_as_uint(Asb[(r0 + 8) * GLD + kk * 8 + lr]);
                af[mi][2] = __float_as_uint(Asb[r0 * GLD + kk * 8 + lr + 4]);
                af[mi][3] = __float_as_uint(Asb[(r0 + 8) * GLD + kk * 8 + lr + 4]);
            }
#pragma unroll
            for (int ni = 0; ni < 4; ni++) {
                int c0 = wn * 32 + ni * 8 + lg;
                if (bcvt) {
                    bf[ni][0] = f2tf(Bsb[c0 * GLD + kk * 8 + lr]);
                    bf[ni][1] = f2tf(Bsb[c0 * GLD + kk * 8 + lr + 4]);
                } else {
                    bf[ni][0] = __float_as_uint(Bsb[c0 * GLD + kk * 8 + lr]);
                    bf[ni][1] = __float_as_uint(Bsb[c0 * GLD + kk * 8 + lr + 4]);
                }
            }
#pragma unroll
            for (int mi = 0; mi < 2; mi++)
#pragma unroll
                for (int ni = 0; ni < 4; ni++)
                    mma_tf32(acc[mi][ni], af[mi], bf[ni][0], bf[ni][1]);
        }
    }

    // direct epilogue from registers
#pragma unroll
    for (int mi = 0; mi < 2; mi++) {
        int pos0 = i0 + wm * 32 + mi * 16 + lg;
        int pos1 = pos0 + 8;
        bool v0 = pos0 < Mz, v1 = pos1 < Mz;
        int cr0 = v0 ? (rowmap ? rowmap[pos0] : pos0) : 0;
        int cr1 = v1 ? (rowmap ? rowmap[pos1] : pos1) : 0;
#pragma unroll
        for (int ni = 0; ni < 4; ni++) {
            int col = j0 + wn * 32 + ni * 8 + lr * 2;
            float b0v = 0.f, b1v = 0.f;
            if (bias) { b0v = bias[(long)e * N + col]; b1v = bias[(long)e * N + col + 1]; }
            if (v0) {
                float x0 = acc[mi][ni][0] + b0v, x1 = acc[mi][ni][1] + b1v;
                if (relu) { x0 = fmaxf(x0, 0.f); x1 = fmaxf(x1, 0.f); }
                if (res) { x0 += res[(long)cr0 * N + col]; x1 += res[(long)cr0 * N + col + 1]; }
                if (cvt_out) { x0 = tfr(x0); x1 = tfr(x1); }
                *(float2*)&C[(long)cr0 * N + col] = make_float2(x0, x1);
            }
            if (v1) {
                float x0 = acc[mi][ni][2] + b0v, x1 = acc[mi][ni][3] + b1v;
                if (relu) { x0 = fmaxf(x0, 0.f); x1 = fmaxf(x1, 0.f); }
                if (res) { x0 += res[(long)cr1 * N + col]; x1 += res[(long)cr1 * N + col + 1]; }
                if (cvt_out) { x0 = tfr(x0); x1 = tfr(x1); }
                *(float2*)&C[(long)cr1 * N + col] = make_float2(x0, x1);
            }
        }
    }
}

// ---------------- fused flash attention (tf32 mma; Q/K/V pre-rounded) -------------
#define FA_LD 68
#define FA_SMEM (3 * 64 * FA_LD * 4)

__global__ __launch_bounds__(128) void flash_attn_kernel(
    const float* __restrict__ Q, const float* __restrict__ Kg,
    const float* __restrict__ Vg, float* __restrict__ O) {
    extern __shared__ float sm[];
    float* Ks = sm;
    float* Vs = sm + 64 * FA_LD;
    float* Ps = sm + 2 * 64 * FA_LD;

    int qt = blockIdx.x;
    int z  = blockIdx.y;
    int b  = z >> 4, h = z & 15;
    int q0 = qt * 64;
    int tid = threadIdx.x, warp = tid >> 5, lane = tid & 31;
    int lg = lane >> 2, lr = lane & 3;

    const float* Qb = Q  + (long)(b * Tdim) * DM + h * HD;
    const float* Kb = Kg + (long)(b * Tdim) * DM + h * HD;
    const float* Vb = Vg + (long)(b * Tdim) * DM + h * HD;

    for (int it = tid; it < 64 * 16; it += 128) {
        int r = it >> 4, c4 = it & 15;
        *(float4*)&Ps[r * FA_LD + c4 * 4] = *(const float4*)(Qb + (long)(q0 + r) * DM + c4 * 4);
    }
    __syncthreads();
    unsigned qa[8][4];
    int rlo = warp * 16 + lg;
#pragma unroll
    for (int ks = 0; ks < 8; ks++) {
        qa[ks][0] = __float_as_uint(Ps[(rlo)     * FA_LD + ks * 8 + lr]);
        qa[ks][1] = __float_as_uint(Ps[(rlo + 8) * FA_LD + ks * 8 + lr]);
        qa[ks][2] = __float_as_uint(Ps[(rlo)     * FA_LD + ks * 8 + lr + 4]);
        qa[ks][3] = __float_as_uint(Ps[(rlo + 8) * FA_LD + ks * 8 + lr + 4]);
    }

    float o[8][4];
#pragma unroll
    for (int nf = 0; nf < 8; nf++)
#pragma unroll
        for (int e = 0; e < 4; e++) o[nf][e] = 0.f;
    float m_lo = -1e30f, m_hi = -1e30f, l_lo = 0.f, l_hi = 0.f;

    int row_lo = q0 + warp * 16 + lg;
    int row_hi = row_lo + 8;

    for (int kc = 0; kc <= qt; kc++) {
        __syncthreads();
        for (int it = tid; it < 64 * 16; it += 128) {
            int r = it >> 4, c4 = it & 15;
            *(float4*)&Ks[r * FA_LD + c4 * 4] = *(const float4*)(Kb + (long)(kc * 64 + r) * DM + c4 * 4);
            *(float4*)&Vs[r * FA_LD + c4 * 4] = *(const float4*)(Vb + (long)(kc * 64 + r) * DM + c4 * 4);
        }
        __syncthreads();

        float s[8][4];
#pragma unroll
        for (int nf = 0; nf < 8; nf++)
#pragma unroll
            for (int e = 0; e < 4; e++) s[nf][e] = 0.f;
#pragma unroll
        for (int ks = 0; ks < 8; ks++) {
#pragma unroll
            for (int nf = 0; nf < 8; nf++) {
                unsigned b0 = __float_as_uint(Ks[(nf * 8 + lg) * FA_LD + ks * 8 + lr]);
                unsigned b1 = __float_as_uint(Ks[(nf * 8 + lg) * FA_LD + ks * 8 + lr + 4]);
                mma_tf32(s[nf], qa[ks], b0, b1);
            }
        }

        int colbase = kc * 64 + lr * 2;
#pragma unroll
        for (int nf = 0; nf < 8; nf++) {
            int c0 = colbase + nf * 8;
            s[nf][0] = (c0     <= row_lo) ? s[nf][0] * 0.125f : -1e30f;
            s[nf][1] = (c0 + 1 <= row_lo) ? s[nf][1] * 0.125f : -1e30f;
            s[nf][2] = (c0     <= row_hi) ? s[nf][2] * 0.125f : -1e30f;
            s[nf][3] = (c0 + 1 <= row_hi) ? s[nf][3] * 0.125f : -1e30f;
        }

        float cm_lo = -1e30f, cm_hi = -1e30f;
#pragma unroll
        for (int nf = 0; nf < 8; nf++) {
            cm_lo = fmaxf(cm_lo, fmaxf(s[nf][0], s[nf][1]));
            cm_hi = fmaxf(cm_hi, fmaxf(s[nf][2], s[nf][3]));
        }
        cm_lo = fmaxf(cm_lo, __shfl_xor_sync(0xffffffffu, cm_lo, 1));
        cm_lo = fmaxf(cm_lo, __shfl_xor_sync(0xffffffffu, cm_lo, 2));
        cm_hi = fmaxf(cm_hi, __shfl_xor_sync(0xffffffffu, cm_hi, 1));
        cm_hi = fmaxf(cm_hi, __shfl_xor_sync(0xffffffffu, cm_hi, 2));

        float nm_lo = fmaxf(m_lo, cm_lo), nm_hi = fmaxf(m_hi, cm_hi);
        float al_lo = __expf(m_lo - nm_lo), al_hi = __expf(m_hi - nm_hi);
        m_lo = nm_lo; m_hi = nm_hi;

        float ps_lo = 0.f, ps_hi = 0.f;
#pragma unroll
        for (int nf = 0; nf < 8; nf++) {
            s[nf][0] = __expf(s[nf][0] - m_lo);
            s[nf][1] = __expf(s[nf][1] - m_lo);
            s[nf][2] = __expf(s[nf][2] - m_hi);
            s[nf][3] = __expf(s[nf][3] - m_hi);
            ps_lo += s[nf][0] + s[nf][1];
            ps_hi += s[nf][2] + s[nf][3];
        }
        ps_lo += __shfl_xor_sync(0xffffffffu, ps_lo, 1);
        ps_lo += __shfl_xor_sync(0xffffffffu, ps_lo, 2);
        ps_hi += __shfl_xor_sync(0xffffffffu, ps_hi, 1);
        ps_hi += __shfl_xor_sync(0xffffffffu, ps_hi, 2);
        l_lo = l_lo * al_lo + ps_lo;
        l_hi = l_hi * al_hi + ps_hi;

#pragma unroll
        for (int nf = 0; nf < 8; nf++) {
            o[nf][0] *= al_lo; o[nf][1] *= al_lo;
            o[nf][2] *= al_hi; o[nf][3] *= al_hi;
        }

        int prl = warp * 16 + lg;
#pragma unroll
        for (int nf = 0; nf < 8; nf++) {
            Ps[(prl)     * FA_LD + nf * 8 + lr * 2]     = tfr(s[nf][0]);
            Ps[(prl)     * FA_LD + nf * 8 + lr * 2 + 1] = tfr(s[nf][1]);
            Ps[(prl + 8) * FA_LD + nf * 8 + lr * 2]     = tfr(s[nf][2]);
            Ps[(prl + 8) * FA_LD + nf * 8 + lr * 2 + 1] = tfr(s[nf][3]);
        }
        __syncwarp();

#pragma unroll
        for (int ks = 0; ks < 8; ks++) {
            unsigned pa[4];
            pa[0] = __float_as_uint(Ps[(prl)     * FA_LD + ks * 8 + lr]);
            pa[1] = __float_as_uint(Ps[(prl + 8) * FA_LD + ks * 8 + lr]);
            pa[2] = __float_as_uint(Ps[(prl)     * FA_LD + ks * 8 + lr + 4]);
            pa[3] = __float_as_uint(Ps[(prl + 8) * FA_LD + ks * 8 + lr + 4]);
#pragma unroll
            for (int nf = 0; nf < 8; nf++) {
                unsigned b0 = __float_as_uint(Vs[(ks * 8 + lr)     * FA_LD + nf * 8 + lg]);
                unsigned b1 = __float_as_uint(Vs[(ks * 8 + lr + 4) * FA_LD + nf * 8 + lg]);
                mma_tf32(o[nf], pa, b0, b1);
            }
        }
    }

    float inv_lo = 1.f / l_lo, inv_hi = 1.f / l_hi;
    long out_lo = (long)(b * Tdim + row_lo) * DM + h * HD;
    long out_hi = (long)(b * Tdim + row_hi) * DM + h * HD;
#pragma unroll
    for (int nf = 0; nf < 8; nf++) {
        int c = nf * 8 + lr * 2;
        *(float2*)&O[out_lo + c] = make_float2(tfr(o[nf][0] * inv_lo), tfr(o[nf][1] * inv_lo));
        *(float2*)&O[out_hi + c] = make_float2(tfr(o[nf][2] * inv_hi), tfr(o[nf][3] * inv_hi));
    }
}

// ---------------- launch ----------------
extern "C" void kernel_launch(void* const* d_in, const int* in_sizes, int n_in,
                              void* d_out, int out_size) {
    const float* x       = (const float*)d_in[0];
    const float* norm1_w = (const float*)d_in[1];
    const float* norm2_w = (const float*)d_in[2];
    const float* Wq      = (const float*)d_in[3];
    const float* Wdkv    = (const float*)d_in[4];
    const float* Wuk     = (const float*)d_in[5];
    const float* Wuv     = (const float*)d_in[6];
    const float* Wo      = (const float*)d_in[7];
    const float* ln_g    = (const float*)d_in[8];
    const float* ln_b    = (const float*)d_in[9];
    const float* gate_w  = (const float*)d_in[10];
    const float* gate_b  = (const float*)d_in[11];
    const float* W1      = (const float*)d_in[12];
    const float* b1      = (const float*)d_in[13];
    const float* W2      = (const float*)d_in[14];
    const float* b2      = (const float*)d_in[15];
    float* out = (float*)d_out;

    float *p_xn, *p_q, *p_lat, *p_k, *p_v, *p_attn, *p_x1, *p_xn2, *p_h;
    float *p_wq, *p_wdkv, *p_wuk, *p_wuv, *p_wo;
    cudaGetSymbolAddress((void**)&p_xn,  g_xn);
    cudaGetSymbolAddress((void**)&p_q,   g_q);
    cudaGetSymbolAddress((void**)&p_lat, g_lat);
    cudaGetSymbolAddress((void**)&p_k,   g_k);
    cudaGetSymbolAddress((void**)&p_v,   g_v);
    cudaGetSymbolAddress((void**)&p_attn,g_attn);
    cudaGetSymbolAddress((void**)&p_x1,  g_x1);
    cudaGetSymbolAddress((void**)&p_xn2, g_xn2);
    cudaGetSymbolAddress((void**)&p_h,   g_h);
    cudaGetSymbolAddress((void**)&p_wq,  g_wq);
    cudaGetSymbolAddress((void**)&p_wdkv,g_wdkv);
    cudaGetSymbolAddress((void**)&p_wuk, g_wuk);
    cudaGetSymbolAddress((void**)&p_wuv, g_wuv);
    cudaGetSymbolAddress((void**)&p_wo,  g_wo);

    cudaFuncSetAttribute(flash_attn_kernel, cudaFuncAttributeMaxDynamicSharedMemorySize, FA_SMEM);
    cudaFuncSetAttribute(gemm_tf32, cudaFuncAttributeMaxDynamicSharedMemorySize, GEMM_SMEM);

    // 0. pre-round small attention weights (one launch, 14MB)
    cvtw5_kernel<<<(NW_TOTAL + 255) / 256, 256>>>(Wq, Wdkv, Wuk, Wuv, Wo);

    // 1. xn = rmsnorm(x)  [tf32]
    rmsnorm_kernel<<<BT, 256>>>(x, norm1_w, p_xn);
    // 2. q = xn @ Wq^T
    gemm_tf32<<<dim3(DM/128, BT/128, 1), 512, GEMM_SMEM>>>(p_xn, p_wq, p_q, BT, DM, DM, nullptr, nullptr, 0, 0, 0, 0, 0);
    // 3. lat = layernorm(xn @ Wdkv^T)  [tf32 in place]
    gemm_tf32<<<dim3(KVL/128, BT/128, 1), 512, GEMM_SMEM>>>(p_xn, p_wdkv, p_lat, BT, KVL, DM, nullptr, nullptr, 0, 0, 0, 0, 0);
    layernorm_kernel<<<BT, 256>>>(p_lat, ln_g, ln_b);
    // 4. k, v  (v rounded at epilogue; q,k rounded by rope)
    gemm_tf32<<<dim3(DM/128, BT/128, 1), 512, GEMM_SMEM>>>(p_lat, p_wuk, p_k, BT, DM, KVL, nullptr, nullptr, 0, 0, 0, 0, 0);
    gemm_tf32<<<dim3(DM/128, BT/128, 1), 512, GEMM_SMEM>>>(p_lat, p_wuv, p_v, BT, DM, KVL, nullptr, nullptr, 0, 0, 0, 0, 1);
    // 5. RoPE on q and k  [tf32]
    rope_kernel<<<dim3(4096, 2), 256>>>(p_q, p_k);
    // 6. fused flash attention  [attn tf32]
    flash_attn_kernel<<<dim3(Tdim/64, 32), 128, FA_SMEM>>>(p_q, p_k, p_v, p_attn);
    // 7. x1 = x + attn @ Wo^T  [full fp32 residual]
    gemm_tf32<<<dim3(DM/128, BT/128, 1), 512, GEMM_SMEM>>>(p_attn, p_wo, p_x1, BT, DM, DM, nullptr, x, 0, 0, 0, 0, 0);
    // 8. xn2 = rmsnorm(x1)  [tf32]
    rmsnorm_kernel<<<BT, 256>>>(p_x1, norm2_w, p_xn2);
    // 9. gating
    zero_cnt_kernel<<<1, 32>>>();
    gate_kernel<<<BT, 128>>>(p_xn2, gate_w, gate_b);
    // 10. MoE expert GEMMs (W1/W2 NOT pre-rounded: bcvt=1; h rounded at epilogue)
    gemm_tf32<<<dim3(DH/128, BT/128, NE), 512, GEMM_SMEM>>>(p_xn2, W1, p_h, BT, DH, DM, b1, nullptr, 1, 1, (long)DH * DM, 1, 1);
    gemm_tf32<<<dim3(DM/128, BT/128, NE), 512, GEMM_SMEM>>>(p_h, W2, out, BT, DM, DH, b2, p_x1, 0, 1, (long)DM * DH, 1, 0);
    (void)in_sizes; (void)n_in; (void)out_size;
}

// round 16
// speedup vs baseline: 1.6023x; 1.6023x over previous
#include <cuda_runtime.h>
#include <cuda_fp16.h>
#include <math.h>

#define Tdim 1024
#define BT   2048   // B*T
#define DM   1024
#define NH   16
#define HD   64
#define KVL  512
#define NE   4
#define DH   4096

// ---------------- scratch (device globals; no runtime allocation) ----------------
__device__ __half g_xn_h  [BT*DM];
__device__ float  g_q   [BT*DM];
__device__ float  g_lat [BT*KVL];
__device__ __half g_lat_h[BT*KVL];
__device__ float  g_k   [BT*DM];
__device__ float  g_v   [BT*DM];
__device__ __half g_attn_h[BT*DM];
__device__ float  g_x1  [BT*DM];
__device__ float  g_xn2 [BT*DM];
__device__ float  g_h   [BT*DH];
__device__ int    g_cnt [NE];
__device__ int    g_idx [NE*BT];
// half copies of the small attention weights (7MB total)
__device__ __half g_wq_h  [DM*DM];
__device__ __half g_wdkv_h[KVL*DM];
__device__ __half g_wuk_h [DM*KVL];
__device__ __half g_wuv_h [DM*KVL];
__device__ __half g_wo_h  [DM*DM];

// ---------------- helpers ----------------
__device__ __forceinline__ unsigned f2tf(float x) {
    unsigned r; asm("cvt.rna.tf32.f32 %0, %1;" : "=r"(r) : "f"(x)); return r;
}
__device__ __forceinline__ float tfr(float x) { return __uint_as_float(f2tf(x)); }
__device__ __forceinline__ void mma_tf32(float* c, const unsigned* a, unsigned b0, unsigned b1) {
    asm volatile(
        "mma.sync.aligned.m16n8k8.row.col.f32.tf32.tf32.f32 "
        "{%0,%1,%2,%3}, {%4,%5,%6,%7}, {%8,%9}, {%0,%1,%2,%3};"
        : "+f"(c[0]), "+f"(c[1]), "+f"(c[2]), "+f"(c[3])
        : "r"(a[0]), "r"(a[1]), "r"(a[2]), "r"(a[3]), "r"(b0), "r"(b1));
}
__device__ __forceinline__ void mma_f16(float* c, const unsigned* a, unsigned b0, unsigned b1) {
    asm volatile(
        "mma.sync.aligned.m16n8k16.row.col.f32.f16.f16.f32 "
        "{%0,%1,%2,%3}, {%4,%5,%6,%7}, {%8,%9}, {%0,%1,%2,%3};"
        : "+f"(c[0]), "+f"(c[1]), "+f"(c[2]), "+f"(c[3])
        : "r"(a[0]), "r"(a[1]), "r"(a[2]), "r"(a[3]), "r"(b0), "r"(b1));
}
__device__ __forceinline__ void cp_async16(unsigned dst, const void* src, int srcbytes) {
    asm volatile("cp.async.cg.shared.global [%0], [%1], 16, %2;"
                 :: "r"(dst), "l"(src), "r"(srcbytes));
}
__device__ __forceinline__ void cp_commit() { asm volatile("cp.async.commit_group;"); }
__device__ __forceinline__ void cp_wait0()  { asm volatile("cp.async.wait_group 0;"); }

// ---------------- small-weight fp32 -> fp16 (one launch) ----------------
#define NWQ   (DM*DM)
#define NWDKV (KVL*DM)
#define NWUK  (DM*KVL)
#define NWUV  (DM*KVL)
#define NWO   (DM*DM)
#define NW_TOTAL (NWQ + NWDKV + NWUK + NWUV + NWO)

__global__ __launch_bounds__(256) void cvtw5_kernel(
    const float* __restrict__ wq, const float* __restrict__ wdkv,
    const float* __restrict__ wuk, const float* __restrict__ wuv,
    const float* __restrict__ wo) {
    int i = blockIdx.x * 256 + threadIdx.x;
    if (i >= NW_TOTAL) return;
    if (i < NWQ) { g_wq_h[i] = __float2half_rn(wq[i]); return; }
    i -= NWQ;
    if (i < NWDKV) { g_wdkv_h[i] = __float2half_rn(wdkv[i]); return; }
    i -= NWDKV;
    if (i < NWUK) { g_wuk_h[i] = __float2half_rn(wuk[i]); return; }
    i -= NWUK;
    if (i < NWUV) { g_wuv_h[i] = __float2half_rn(wuv[i]); return; }
    i -= NWUV;
    g_wo_h[i] = __float2half_rn(wo[i]);
}

// ---------------- elementwise ----------------
// rmsnorm -> half output (feeds fp16 GEMMs)
__global__ __launch_bounds__(256) void rmsnorm_h_kernel(
    const float* __restrict__ x, const float* __restrict__ w, __half* __restrict__ out) {
    int row = blockIdx.x, tid = threadIdx.x;
    const float* xr = x + (long)row * DM;
    float ss = 0.f;
    for (int d = tid; d < DM; d += 256) { float v = xr[d]; ss += v * v; }
    __shared__ float red[256];
    red[tid] = ss; __syncthreads();
    for (int s = 128; s > 0; s >>= 1) { if (tid < s) red[tid] += red[tid + s]; __syncthreads(); }
    float scale = rsqrtf(red[0] / DM + 1e-6f);
    for (int d = tid; d < DM; d += 256) out[(long)row * DM + d] = __float2half_rn(w[d] * xr[d] * scale);
}

// rmsnorm -> fp32 tf32-rounded output (feeds tf32 MoE GEMM + gate)
__global__ __launch_bounds__(256) void rmsnorm_f_kernel(
    const float* __restrict__ x, const float* __restrict__ w, float* __restrict__ out) {
    int row = blockIdx.x, tid = threadIdx.x;
    const float* xr = x + (long)row * DM;
    float ss = 0.f;
    for (int d = tid; d < DM; d += 256) { float v = xr[d]; ss += v * v; }
    __shared__ float red[256];
    red[tid] = ss; __syncthreads();
    for (int s = 128; s > 0; s >>= 1) { if (tid < s) red[tid] += red[tid + s]; __syncthreads(); }
    float scale = rsqrtf(red[0] / DM + 1e-6f);
    for (int d = tid; d < DM; d += 256) out[(long)row * DM + d] = tfr(w[d] * xr[d] * scale);
}

// layernorm: fp32 in, half out
__global__ __launch_bounds__(256) void layernorm_h_kernel(
    const float* __restrict__ p, const float* __restrict__ g, const float* __restrict__ b,
    __half* __restrict__ out) {
    int row = blockIdx.x, tid = threadIdx.x;
    const float* xr = p + (long)row * KVL;
    __shared__ float red[256];
    float s = 0.f;
    for (int d = tid; d < KVL; d += 256) s += xr[d];
    red[tid] = s; __syncthreads();
    for (int k = 128; k > 0; k >>= 1) { if (tid < k) red[tid] += red[tid + k]; __syncthreads(); }
    float mu = red[0] / KVL;
    __syncthreads();
    float vs = 0.f;
    for (int d = tid; d < KVL; d += 256) { float dv = xr[d] - mu; vs += dv * dv; }
    red[tid] = vs; __syncthreads();
    for (int k = 128; k > 0; k >>= 1) { if (tid < k) red[tid] += red[tid + k]; __syncthreads(); }
    float inv = rsqrtf(red[0] / KVL + 1e-5f);
    for (int d = tid; d < KVL; d += 256)
        out[(long)row * KVL + d] = __float2half_rn((xr[d] - mu) * inv * g[d] + b[d]);
}

// one launch, grid.y: 0 -> q, 1 -> k  (fp32, tf32-rounded for flash)
__global__ __launch_bounds__(256) void rope_kernel(float* __restrict__ q, float* __restrict__ k) {
    float* p = blockIdx.y ? k : q;
    int id = blockIdx.x * 256 + threadIdx.x;
    int row = id >> 9;
    int rem = id & 511;
    int h = rem >> 5, d = rem & 31;
    int t = row & (Tdim - 1);
    float* base = p + (long)row * DM + h * HD + d;
    float x1 = base[0], x2 = base[32];
    float inv = powf(10000.f, -(float)d / 32.f);
    float ang = (float)t * inv;
    float sn = sinf(ang), cs = cosf(ang);
    base[0]  = tfr(x1 * cs - x2 * sn);
    base[32] = tfr(x1 * sn + x2 * cs);
}

__global__ void zero_cnt_kernel() { if (threadIdx.x < NE) g_cnt[threadIdx.x] = 0; }

__global__ __launch_bounds__(128) void gate_kernel(
    const float* __restrict__ xn2, const float* __restrict__ gw, const float* __restrict__ gb) {
    int row = blockIdx.x, tid = threadIdx.x;
    const float* xr = xn2 + (long)row * DM;
    float a0 = 0.f, a1 = 0.f, a2 = 0.f, a3 = 0.f;
    for (int d = tid; d < DM; d += 128) {
        float xv = xr[d];
        a0 += xv * gw[d]; a1 += xv * gw[DM + d]; a2 += xv * gw[2 * DM + d]; a3 += xv * gw[3 * DM + d];
    }
    __shared__ float red[4][128];
    red[0][tid] = a0; red[1][tid] = a1; red[2][tid] = a2; red[3][tid] = a3;
    __syncthreads();
    for (int s = 64; s > 0; s >>= 1) {
        if (tid < s) { for (int e = 0; e < 4; e++) red[e][tid] += red[e][tid + s]; }
        __syncthreads();
    }
    if (tid == 0) {
        float l0 = red[0][0] + gb[0], l1 = red[1][0] + gb[1];
        float l2 = red[2][0] + gb[2], l3 = red[3][0] + gb[3];
        int best = 0; float bv = l0;
        if (l1 > bv) { bv = l1; best = 1; }
        if (l2 > bv) { bv = l2; best = 2; }
        if (l3 > bv) { bv = l3; best = 3; }
        int pos = atomicAdd(&g_cnt[best], 1);
        g_idx[best * BT + pos] = row;
    }
}

// ---------------- fp16 mma GEMM (attention projections) ----------------
// C[M,N] = A[M,K] * B[N,K]^T, A/B half, C fp32. Block 128x128x32, 512 threads,
// 16 warps (4x4), warp tile 32x32, mma m16n8k16 (2 kk per slab), 2-stage cp.async.
// M, N, K all multiples of 128/128/32 in our uses (no bounds/rowmap needed).
#define FLDH 40                                // halves per smem row (conflict-free)
#define FSTG (2 * 128 * FLDH)                  // halves per stage (A+B)
#define F16_SMEM (2 * FSTG * 2)                // bytes: 2 stages

__global__ __launch_bounds__(512) void gemm_f16(
    const __half* __restrict__ A, const __half* __restrict__ Bw, float* __restrict__ C,
    int M, int N, int K, const float* __restrict__ res, int cvt_out) {
    extern __shared__ __half hsm[];
    unsigned sbase = (unsigned)__cvta_generic_to_shared(hsm);

    int i0 = blockIdx.y * 128;
    int j0 = blockIdx.x * 128;
    int tid = threadIdx.x;
    int warp = tid >> 5, lane = tid & 31;
    int wm = warp >> 2, wn = warp & 3;
    int lg = lane >> 2, lr = lane & 3;

    float acc[2][4][4];
#pragma unroll
    for (int mi = 0; mi < 2; mi++)
#pragma unroll
        for (int ni = 0; ni < 4; ni++)
#pragma unroll
            for (int q = 0; q < 4; q++) acc[mi][ni][q] = 0.f;

    int KT = K / 32;
    int lrow = tid >> 2, lc = tid & 3;         // 128 rows x 4 chunks (16B = 8 halves)

    // issue tile 0
    {
        unsigned adst = sbase;
        unsigned bdst = sbase + 128 * FLDH * 2;
        cp_async16(adst + (lrow * FLDH + lc * 8) * 2, A + (long)(i0 + lrow) * K + lc * 8, 16);
        cp_async16(bdst + (lrow * FLDH + lc * 8) * 2, Bw + (long)(j0 + lrow) * K + lc * 8, 16);
        cp_commit();
    }

    for (int kt = 0; kt < KT; kt++) {
        cp_wait0();
        __syncthreads();
        if (kt + 1 < KT) {
            int nb = (kt + 1) & 1;
            int k0 = (kt + 1) * 32;
            unsigned adst = sbase + nb * FSTG * 2;
            unsigned bdst = adst + 128 * FLDH * 2;
            cp_async16(adst + (lrow * FLDH + lc * 8) * 2, A + (long)(i0 + lrow) * K + k0 + lc * 8, 16);
            cp_async16(bdst + (lrow * FLDH + lc * 8) * 2, Bw + (long)(j0 + lrow) * K + k0 + lc * 8, 16);
            cp_commit();
        }
        const __half* Ah = hsm + (kt & 1) * FSTG;
        const __half* Bh = Ah + 128 * FLDH;
#pragma unroll
        for (int kk = 0; kk < 2; kk++) {
            unsigned af[2][4], bf[4][2];
#pragma unroll
            for (int mi = 0; mi < 2; mi++) {
                int r0 = wm * 32 + mi * 16 + lg;
                af[mi][0] = *(const unsigned*)&Ah[r0 * FLDH + kk * 16 + lr * 2];
                af[mi][1] = *(const unsigned*)&Ah[(r0 + 8) * FLDH + kk * 16 + lr * 2];
                af[mi][2] = *(const unsigned*)&Ah[r0 * FLDH + kk * 16 + 8 + lr * 2];
                af[mi][3] = *(const unsigned*)&Ah[(r0 + 8) * FLDH + kk * 16 + 8 + lr * 2];
            }
#pragma unroll
            for (int ni = 0; ni < 4; ni++) {
                int c0 = wn * 32 + ni * 8 + lg;
                bf[ni][0] = *(const unsigned*)&Bh[c0 * FLDH + kk * 16 + lr * 2];
                bf[ni][1] = *(const unsigned*)&Bh[c0 * FLDH + kk * 16 + 8 + lr * 2];
            }
#pragma unroll
            for (int mi = 0; mi < 2; mi++)
#pragma unroll
                for (int ni = 0; ni < 4; ni++)
                    mma_f16(acc[mi][ni], af[mi], bf[ni][0], bf[ni][1]);
        }
    }

    // epilogue
#pragma unroll
    for (int mi = 0; mi < 2; mi++) {
        int r0 = i0 + wm * 32 + mi * 16 + lg;
        int r1 = r0 + 8;
#pragma unroll
        for (int ni = 0; ni < 4; ni++) {
            int col = j0 + wn * 32 + ni * 8 + lr * 2;
            float x0 = acc[mi][ni][0], x1 = acc[mi][ni][1];
            float y0 = acc[mi][ni][2], y1 = acc[mi][ni][3];
            if (res) {
                x0 += res[(long)r0 * N + col]; x1 += res[(long)r0 * N + col + 1];
                y0 += res[(long)r1 * N + col]; y1 += res[(long)r1 * N + col + 1];
            }
            if (cvt_out) { x0 = tfr(x0); x1 = tfr(x1); y0 = tfr(y0); y1 = tfr(y1); }
            *(float2*)&C[(long)r0 * N + col] = make_float2(x0, x1);
            *(float2*)&C[(long)r1 * N + col] = make_float2(y0, y1);
        }
    }
}

// ---------------- tf32 mma GEMM (MoE; unchanged from R12 champion) ----------------
#define GBM 128
#define GBN 128
#define GBK 32
#define GLD 36
#define GEMM_SMEM (4 * 128 * GLD * 4)

__global__ __launch_bounds__(512) void gemm_tf32(
    const float* __restrict__ A, const float* __restrict__ Bw, float* __restrict__ C,
    int M, int N, int K,
    const float* __restrict__ bias, const float* __restrict__ res,
    int relu, int use_idx, long wstride, int bcvt, int cvt_out) {
    extern __shared__ float sm[];
    unsigned sbase = (unsigned)__cvta_generic_to_shared(sm);

    int e = blockIdx.z;
    const float* Bm = Bw + (long)e * wstride;
    int Mz = M;
    const int* rowmap = nullptr;
    if (use_idx) { Mz = g_cnt[e]; rowmap = g_idx + e * BT; }
    int i0 = blockIdx.y * GBM;
    if (i0 >= Mz) return;
    int j0 = blockIdx.x * GBN;

    int tid = threadIdx.x;
    int warp = tid >> 5, lane = tid & 31;
    int wm = warp >> 2, wn = warp & 3;
    int lg = lane >> 2, lr = lane & 3;

    int arows[2]; int asz[2];
#pragma unroll
    for (int it = 0; it < 2; it++) {
        int r = (tid + it * 512) >> 3;
        int pos = i0 + r;
        bool v = pos < Mz;
        asz[it] = v ? 16 : 0;
        arows[it] = rowmap ? (v ? rowmap[pos] : 0) : pos;
    }

    float acc[2][4][4];
#pragma unroll
    for (int mi = 0; mi < 2; mi++)
#pragma unroll
        for (int ni = 0; ni < 4; ni++)
#pragma unroll
            for (int q = 0; q < 4; q++) acc[mi][ni][q] = 0.f;

    int KT = K / GBK;

    {
        unsigned adst = sbase;
        unsigned bdst = sbase + 128 * GLD * 4;
#pragma unroll
        for (int it = 0; it < 2; it++) {
            int f = tid + it * 512;
            int r = f >> 3, c4 = f & 7;
            cp_async16(adst + (r * GLD + c4 * 4) * 4, A + (long)arows[it] * K + c4 * 4, asz[it]);
            cp_async16(bdst + (r * GLD + c4 * 4) * 4, Bm + (long)(j0 + r) * K + c4 * 4, 16);
        }
        cp_commit();
    }

    for (int kt = 0; kt < KT; kt++) {
        cp_wait0();
        __syncthreads();
        if (kt + 1 < KT) {
            int nb = (kt + 1) & 1;
            int k0 = (kt + 1) * GBK;
            unsigned adst = sbase + (nb * 2) * 128 * GLD * 4;
            unsigned bdst = sbase + (nb * 2 + 1) * 128 * GLD * 4;
#pragma unroll
            for (int it = 0; it < 2; it++) {
                int f = tid + it * 512;
                int r = f >> 3, c4 = f & 7;
                cp_async16(adst + (r * GLD + c4 * 4) * 4, A + (long)arows[it] * K + k0 + c4 * 4, asz[it]);
                cp_async16(bdst + (r * GLD + c4 * 4) * 4, Bm + (long)(j0 + r) * K + k0 + c4 * 4, 16);
            }
            cp_commit();
        }
        const float* Asb = sm + (kt & 1) * 2 * 128 * GLD;
        const float* Bsb = Asb + 128 * GLD;
#pragma unroll
        for (int kk = 0; kk < 4; kk++) {
            unsigned af[2][4], bf[4][2];
#pragma unroll
            for (int mi = 0; mi < 2; mi++) {
                int r0 = wm * 32 + mi * 16 + lg;
                af[mi][0] = __float_as_uint(Asb[r0 * GLD + kk * 8 + lr]);
                af[mi][1] = __float_as_uint(Asb[(r0 + 8) * GLD + kk * 8 + lr]);
                af[mi][2] = __float_as_uint(Asb[r0 * GLD + kk * 8 + lr + 4]);
                af[mi][3] = __float_as_uint(Asb[(r0 + 8) * GLD + kk * 8 + lr + 4]);
            }
#pragma unroll
            for (int ni = 0; ni < 4; ni++) {
                int c0 = wn * 32 + ni * 8 + lg;
                if (bcvt) {
                    bf[ni][0] = f2tf(Bsb[c0 * GLD + kk * 8 + lr]);
                    bf[ni][1] = f2tf(Bsb[c0 * GLD + kk * 8 + lr + 4]);
                } else {
                    bf[ni][0] = __float_as_uint(Bsb[c0 * GLD + kk * 8 + lr]);
                    bf[ni][1] = __float_as_uint(Bsb[c0 * GLD + kk * 8 + lr + 4]);
                }
            }
#pragma unroll
            for (int mi = 0; mi < 2; mi++)
#pragma unroll
                for (int ni = 0; ni < 4; ni++)
                    mma_tf32(acc[mi][ni], af[mi], bf[ni][0], bf[ni][1]);
        }
    }

#pragma unroll
    for (int mi = 0; mi < 2; mi++) {
        int pos0 = i0 + wm * 32 + mi * 16 + lg;
        int pos1 = pos0 + 8;
        bool v0 = pos0 < Mz, v1 = pos1 < Mz;
        int cr0 = v0 ? (rowmap ? rowmap[pos0] : pos0) : 0;
        int cr1 = v1 ? (rowmap ? rowmap[pos1] : pos1) : 0;
#pragma unroll
        for (int ni = 0; ni < 4; ni++) {
            int col = j0 + wn * 32 + ni * 8 + lr * 2;
            float b0v = 0.f, b1v = 0.f;
            if (bias) { b0v = bias[(long)e * N + col]; b1v = bias[(long)e * N + col + 1]; }
            if (v0) {
                float x0 = acc[mi][ni][0] + b0v, x1 = acc[mi][ni][1] + b1v;
                if (relu) { x0 = fmaxf(x0, 0.f); x1 = fmaxf(x1, 0.f); }
                if (res) { x0 += res[(long)cr0 * N + col]; x1 += res[(long)cr0 * N + col + 1]; }
                if (cvt_out) { x0 = tfr(x0); x1 = tfr(x1); }
                *(float2*)&C[(long)cr0 * N + col] = make_float2(x0, x1);
            }
            if (v1) {
                float x0 = acc[mi][ni][2] + b0v, x1 = acc[mi][ni][3] + b1v;
                if (relu) { x0 = fmaxf(x0, 0.f); x1 = fmaxf(x1, 0.f); }
                if (res) { x0 += res[(long)cr1 * N + col]; x1 += res[(long)cr1 * N + col + 1]; }
                if (cvt_out) { x0 = tfr(x0); x1 = tfr(x1); }
                *(float2*)&C[(long)cr1 * N + col] = make_float2(x0, x1);
            }
        }
    }
}

// ---------------- fused flash attention (tf32 mma; output half for Wo GEMM) ------
#define FA_LD 68
#define FA_SMEM (3 * 64 * FA_LD * 4)

__global__ __launch_bounds__(128) void flash_attn_kernel(
    const float* __restrict__ Q, const float* __restrict__ Kg,
    const float* __restrict__ Vg, __half* __restrict__ O) {
    extern __shared__ float sm[];
    float* Ks = sm;
    float* Vs = sm + 64 * FA_LD;
    float* Ps = sm + 2 * 64 * FA_LD;

    int qt = blockIdx.x;
    int z  = blockIdx.y;
    int b  = z >> 4, h = z & 15;
    int q0 = qt * 64;
    int tid = threadIdx.x, warp = tid >> 5, lane = tid & 31;
    int lg = lane >> 2, lr = lane & 3;

    const float* Qb = Q  + (long)(b * Tdim) * DM + h * HD;
    const float* Kb = Kg + (long)(b * Tdim) * DM + h * HD;
    const float* Vb = Vg + (long)(b * Tdim) * DM + h * HD;

    for (int it = tid; it < 64 * 16; it += 128) {
        int r = it >> 4, c4 = it & 15;
        *(float4*)&Ps[r * FA_LD + c4 * 4] = *(const float4*)(Qb + (long)(q0 + r) * DM + c4 * 4);
    }
    __syncthreads();
    unsigned qa[8][4];
    int rlo = warp * 16 + lg;
#pragma unroll
    for (int ks = 0; ks < 8; ks++) {
        qa[ks][0] = __float_as_uint(Ps[(rlo)     * FA_LD + ks * 8 + lr]);
        qa[ks][1] = __float_as_uint(Ps[(rlo + 8) * FA_LD + ks * 8 + lr]);
        qa[ks][2] = __float_as_uint(Ps[(rlo)     * FA_LD + ks * 8 + lr + 4]);
        qa[ks][3] = __float_as_uint(Ps[(rlo + 8) * FA_LD + ks * 8 + lr + 4]);
    }

    float o[8][4];
#pragma unroll
    for (int nf = 0; nf < 8; nf++)
#pragma unroll
        for (int e = 0; e < 4; e++) o[nf][e] = 0.f;
    float m_lo = -1e30f, m_hi = -1e30f, l_lo = 0.f, l_hi = 0.f;

    int row_lo = q0 + warp * 16 + lg;
    int row_hi = row_lo + 8;

    for (int kc = 0; kc <= qt; kc++) {
        __syncthreads();
        for (int it = tid; it < 64 * 16; it += 128) {
            int r = it >> 4, c4 = it & 15;
            *(float4*)&Ks[r * FA_LD + c4 * 4] = *(const float4*)(Kb + (long)(kc * 64 + r) * DM + c4 * 4);
            *(float4*)&Vs[r * FA_LD + c4 * 4] = *(const float4*)(Vb + (long)(kc * 64 + r) * DM + c4 * 4);
        }
        __syncthreads();

        float s[8][4];
#pragma unroll
        for (int nf = 0; nf < 8; nf++)
#pragma unroll
            for (int e = 0; e < 4; e++) s[nf][e] = 0.f;
#pragma unroll
        for (int ks = 0; ks < 8; ks++) {
#pragma unroll
            for (int nf = 0; nf < 8; nf++) {
                unsigned b0 = __float_as_uint(Ks[(nf * 8 + lg) * FA_LD + ks * 8 + lr]);
                unsigned b1 = __float_as_uint(Ks[(nf * 8 + lg) * FA_LD + ks * 8 + lr + 4]);
                mma_tf32(s[nf], qa[ks], b0, b1);
            }
        }

        int colbase = kc * 64 + lr * 2;
#pragma unroll
        for (int nf = 0; nf < 8; nf++) {
            int c0 = colbase + nf * 8;
            s[nf][0] = (c0     <= row_lo) ? s[nf][0] * 0.125f : -1e30f;
            s[nf][1] = (c0 + 1 <= row_lo) ? s[nf][1] * 0.125f : -1e30f;
            s[nf][2] = (c0     <= row_hi) ? s[nf][2] * 0.125f : -1e30f;
            s[nf][3] = (c0 + 1 <= row_hi) ? s[nf][3] * 0.125f : -1e30f;
        }

        float cm_lo = -1e30f, cm_hi = -1e30f;
#pragma unroll
        for (int nf = 0; nf < 8; nf++) {
            cm_lo = fmaxf(cm_lo, fmaxf(s[nf][0], s[nf][1]));
            cm_hi = fmaxf(cm_hi, fmaxf(s[nf][2], s[nf][3]));
        }
        cm_lo = fmaxf(cm_lo, __shfl_xor_sync(0xffffffffu, cm_lo, 1));
        cm_lo = fmaxf(cm_lo, __shfl_xor_sync(0xffffffffu, cm_lo, 2));
        cm_hi = fmaxf(cm_hi, __shfl_xor_sync(0xffffffffu, cm_hi, 1));
        cm_hi = fmaxf(cm_hi, __shfl_xor_sync(0xffffffffu, cm_hi, 2));

        float nm_lo = fmaxf(m_lo, cm_lo), nm_hi = fmaxf(m_hi, cm_hi);
        float al_lo = __expf(m_lo - nm_lo), al_hi = __expf(m_hi - nm_hi);
        m_lo = nm_lo; m_hi = nm_hi;

        float ps_lo = 0.f, ps_hi = 0.f;
#pragma unroll
        for (int nf = 0; nf < 8; nf++) {
            s[nf][0] = __expf(s[nf][0] - m_lo);
            s[nf][1] = __expf(s[nf][1] - m_lo);
            s[nf][2] = __expf(s[nf][2] - m_hi);
            s[nf][3] = __expf(s[nf][3] - m_hi);
            ps_lo += s[nf][0] + s[nf][1];
            ps_hi += s[nf][2] + s[nf][3];
        }
        ps_lo += __shfl_xor_sync(0xffffffffu, ps_lo, 1);
        ps_lo += __shfl_xor_sync(0xffffffffu, ps_lo, 2);
        ps_hi += __shfl_xor_sync(0xffffffffu, ps_hi, 1);
        ps_hi += __shfl_xor_sync(0xffffffffu, ps_hi, 2);
        l_lo = l_lo * al_lo + ps_lo;
        l_hi = l_hi * al_hi + ps_hi;

#pragma unroll
        for (int nf = 0; nf < 8; nf++) {
            o[nf][0] *= al_lo; o[nf][1] *= al_lo;
            o[nf][2] *= al_hi; o[nf][3] *= al_hi;
        }

        int prl = warp * 16 + lg;
#pragma unroll
        for (int nf = 0; nf < 8; nf++) {
            Ps[(prl)     * FA_LD + nf * 8 + lr * 2]     = tfr(s[nf][0]);
            Ps[(prl)     * FA_LD + nf * 8 + lr * 2 + 1] = tfr(s[nf][1]);
            Ps[(prl + 8) * FA_LD + nf * 8 + lr * 2]     = tfr(s[nf][2]);
            Ps[(prl + 8) * FA_LD + nf * 8 + lr * 2 + 1] = tfr(s[nf][3]);
        }
        __syncwarp();

#pragma unroll
        for (int ks = 0; ks < 8; ks++) {
            unsigned pa[4];
            pa[0] = __float_as_uint(Ps[(prl)     * FA_LD + ks * 8 + lr]);
            pa[1] = __float_as_uint(Ps[(prl + 8) * FA_LD + ks * 8 + lr]);
            pa[2] = __float_as_uint(Ps[(prl)     * FA_LD + ks * 8 + lr + 4]);
            pa[3] = __float_as_uint(Ps[(prl + 8) * FA_LD + ks * 8 + lr + 4]);
#pragma unroll
            for (int nf = 0; nf < 8; nf++) {
                unsigned b0 = __float_as_uint(Vs[(ks * 8 + lr)     * FA_LD + nf * 8 + lg]);
                unsigned b1 = __float_as_uint(Vs[(ks * 8 + lr + 4) * FA_LD + nf * 8 + lg]);
                mma_tf32(o[nf], pa, b0, b1);
            }
        }
    }

    float inv_lo = 1.f / l_lo, inv_hi = 1.f / l_hi;
    long out_lo = (long)(b * Tdim + row_lo) * DM + h * HD;
    long out_hi = (long)(b * Tdim + row_hi) * DM + h * HD;
#pragma unroll
    for (int nf = 0; nf < 8; nf++) {
        int c = nf * 8 + lr * 2;
        __half2 vlo = __floats2half2_rn(o[nf][0] * inv_lo, o[nf][1] * inv_lo);
        __half2 vhi = __floats2half2_rn(o[nf][2] * inv_hi, o[nf][3] * inv_hi);
        *(__half2*)&O[out_lo + c] = vlo;
        *(__half2*)&O[out_hi + c] = vhi;
    }
}

// ---------------- launch ----------------
extern "C" void kernel_launch(void* const* d_in, const int* in_sizes, int n_in,
                              void* d_out, int out_size) {
    const float* x       = (const float*)d_in[0];
    const float* norm1_w = (const float*)d_in[1];
    const float* norm2_w = (const float*)d_in[2];
    const float* Wq      = (const float*)d_in[3];
    const float* Wdkv    = (const float*)d_in[4];
    const float* Wuk     = (const float*)d_in[5];
    const float* Wuv     = (const float*)d_in[6];
    const float* Wo      = (const float*)d_in[7];
    const float* ln_g    = (const float*)d_in[8];
    const float* ln_b    = (const float*)d_in[9];
    const float* gate_w  = (const float*)d_in[10];
    const float* gate_b  = (const float*)d_in[11];
    const float* W1      = (const float*)d_in[12];
    const float* b1      = (const float*)d_in[13];
    const float* W2      = (const float*)d_in[14];
    const float* b2      = (const float*)d_in[15];
    float* out = (float*)d_out;

    __half *p_xn_h, *p_lat_h, *p_attn_h, *p_wq_h, *p_wdkv_h, *p_wuk_h, *p_wuv_h, *p_wo_h;
    float *p_q, *p_lat, *p_k, *p_v, *p_x1, *p_xn2, *p_h;
    cudaGetSymbolAddress((void**)&p_xn_h,  g_xn_h);
    cudaGetSymbolAddress((void**)&p_q,     g_q);
    cudaGetSymbolAddress((void**)&p_lat,   g_lat);
    cudaGetSymbolAddress((void**)&p_lat_h, g_lat_h);
    cudaGetSymbolAddress((void**)&p_k,     g_k);
    cudaGetSymbolAddress((void**)&p_v,     g_v);
    cudaGetSymbolAddress((void**)&p_attn_h,g_attn_h);
    cudaGetSymbolAddress((void**)&p_x1,    g_x1);
    cudaGetSymbolAddress((void**)&p_xn2,   g_xn2);
    cudaGetSymbolAddress((void**)&p_h,     g_h);
    cudaGetSymbolAddress((void**)&p_wq_h,  g_wq_h);
    cudaGetSymbolAddress((void**)&p_wdkv_h,g_wdkv_h);
    cudaGetSymbolAddress((void**)&p_wuk_h, g_wuk_h);
    cudaGetSymbolAddress((void**)&p_wuv_h, g_wuv_h);
    cudaGetSymbolAddress((void**)&p_wo_h,  g_wo_h);

    cudaFuncSetAttribute(flash_attn_kernel, cudaFuncAttributeMaxDynamicSharedMemorySize, FA_SMEM);
    cudaFuncSetAttribute(gemm_tf32, cudaFuncAttributeMaxDynamicSharedMemorySize, GEMM_SMEM);
    cudaFuncSetAttribute(gemm_f16, cudaFuncAttributeMaxDynamicSharedMemorySize, F16_SMEM);

    // 0. convert small attention weights to half (one launch, 14MB read / 7MB write)
    cvtw5_kernel<<<(NW_TOTAL + 255) / 256, 256>>>(Wq, Wdkv, Wuk, Wuv, Wo);

    // 1. xn = rmsnorm(x)  [half]
    rmsnorm_h_kernel<<<BT, 256>>>(x, norm1_w, p_xn_h);
    // 2. q = xn @ Wq^T  [fp16 gemm -> fp32]
    gemm_f16<<<dim3(DM/128, BT/128), 512, F16_SMEM>>>(p_xn_h, p_wq_h, p_q, BT, DM, DM, nullptr, 0);
    // 3. lat = layernorm(xn @ Wdkv^T)  [fp16 gemm -> fp32 -> half]
    gemm_f16<<<dim3(KVL/128, BT/128), 512, F16_SMEM>>>(p_xn_h, p_wdkv_h, p_lat, BT, KVL, DM, nullptr, 0);
    layernorm_h_kernel<<<BT, 256>>>(p_lat, ln_g, ln_b, p_lat_h);
    // 4. k, v  [fp16 gemms; v tf32-rounded, q/k rounded by rope]
    gemm_f16<<<dim3(DM/128, BT/128), 512, F16_SMEM>>>(p_lat_h, p_wuk_h, p_k, BT, DM, KVL, nullptr, 0);
    gemm_f16<<<dim3(DM/128, BT/128), 512, F16_SMEM>>>(p_lat_h, p_wuv_h, p_v, BT, DM, KVL, nullptr, 1);
    // 5. RoPE on q and k  [tf32-rounded fp32]
    rope_kernel<<<dim3(4096, 2), 256>>>(p_q, p_k);
    // 6. fused flash attention  [out: half]
    flash_attn_kernel<<<dim3(Tdim/64, 32), 128, FA_SMEM>>>(p_q, p_k, p_v, p_attn_h);
    // 7. x1 = x + attn @ Wo^T  [fp16 gemm + fp32 residual]
    gemm_f16<<<dim3(DM/128, BT/128), 512, F16_SMEM>>>(p_attn_h, p_wo_h, p_x1, BT, DM, DM, x, 0);
    // 8. xn2 = rmsnorm(x1)  [fp32 tf32-rounded, feeds tf32 MoE + gate]
    rmsnorm_f_kernel<<<BT, 256>>>(p_x1, norm2_w, p_xn2);
    // 9. gating
    zero_cnt_kernel<<<1, 32>>>();
    gate_kernel<<<BT, 128>>>(p_xn2, gate_w, gate_b);
    // 10. MoE expert GEMMs (tf32, unchanged; W1/W2 cvt at B-fragment load)
    gemm_tf32<<<dim3(DH/128, BT/128, NE), 512, GEMM_SMEM>>>(p_xn2, W1, p_h, BT, DH, DM, b1, nullptr, 1, 1, (long)DH * DM, 1, 1);
    gemm_tf32<<<dim3(DM/128, BT/128, NE), 512, GEMM_SMEM>>>(p_h, W2, out, BT, DM, DH, b2, p_x1, 0, 1, (long)DM * DH, 1, 0);
    (void)in_sizes; (void)n_in; (void)out_size;
}

// round 17
// speedup vs baseline: 1.7632x; 1.1004x over previous
#include <cuda_runtime.h>
#include <cuda_fp16.h>
#include <math.h>

#define Tdim 1024
#define BT   2048   // B*T
#define DM   1024
#define NH   16
#define HD   64
#define KVL  512
#define NE   4
#define DH   4096

// ---------------- scratch (device globals; no runtime allocation) ----------------
__device__ __half g_xn_h  [BT*DM];
__device__ float  g_q   [BT*DM];
__device__ float  g_lat [BT*KVL];
__device__ __half g_lat_h[BT*KVL];
__device__ float  g_k   [BT*DM];
__device__ float  g_v   [BT*DM];
__device__ __half g_attn_h[BT*DM];
__device__ float  g_x1  [BT*DM];
__device__ float  g_xn2 [BT*DM];
__device__ __half g_xn2_h[BT*DM];
__device__ __half g_h_h [BT*DH];
__device__ int    g_cnt [NE];
__device__ int    g_idx [NE*BT];
// half copies of weights
__device__ __half g_wq_h  [DM*DM];
__device__ __half g_wdkv_h[KVL*DM];
__device__ __half g_wuk_h [DM*KVL];
__device__ __half g_wuv_h [DM*KVL];
__device__ __half g_wo_h  [DM*DM];
__device__ __half g_w1_h  [NE*DH*DM];   // 32MB
__device__ __half g_w2_h  [NE*DM*DH];   // 32MB

// ---------------- helpers ----------------
__device__ __forceinline__ unsigned f2tf(float x) {
    unsigned r; asm("cvt.rna.tf32.f32 %0, %1;" : "=r"(r) : "f"(x)); return r;
}
__device__ __forceinline__ float tfr(float x) { return __uint_as_float(f2tf(x)); }
__device__ __forceinline__ void mma_tf32(float* c, const unsigned* a, unsigned b0, unsigned b1) {
    asm volatile(
        "mma.sync.aligned.m16n8k8.row.col.f32.tf32.tf32.f32 "
        "{%0,%1,%2,%3}, {%4,%5,%6,%7}, {%8,%9}, {%0,%1,%2,%3};"
        : "+f"(c[0]), "+f"(c[1]), "+f"(c[2]), "+f"(c[3])
        : "r"(a[0]), "r"(a[1]), "r"(a[2]), "r"(a[3]), "r"(b0), "r"(b1));
}
__device__ __forceinline__ void mma_f16(float* c, const unsigned* a, unsigned b0, unsigned b1) {
    asm volatile(
        "mma.sync.aligned.m16n8k16.row.col.f32.f16.f16.f32 "
        "{%0,%1,%2,%3}, {%4,%5,%6,%7}, {%8,%9}, {%0,%1,%2,%3};"
        : "+f"(c[0]), "+f"(c[1]), "+f"(c[2]), "+f"(c[3])
        : "r"(a[0]), "r"(a[1]), "r"(a[2]), "r"(a[3]), "r"(b0), "r"(b1));
}
__device__ __forceinline__ void cp_async16(unsigned dst, const void* src, int srcbytes) {
    asm volatile("cp.async.cg.shared.global [%0], [%1], 16, %2;"
                 :: "r"(dst), "l"(src), "r"(srcbytes));
}
__device__ __forceinline__ void cp_commit() { asm volatile("cp.async.commit_group;"); }
__device__ __forceinline__ void cp_wait0()  { asm volatile("cp.async.wait_group 0;"); }

// ---------------- weight conversions ----------------
#define NWQ   (DM*DM)
#define NWDKV (KVL*DM)
#define NWUK  (DM*KVL)
#define NWUV  (DM*KVL)
#define NWO   (DM*DM)
#define NW_TOTAL (NWQ + NWDKV + NWUK + NWUV + NWO)

__global__ __launch_bounds__(256) void cvtw5_kernel(
    const float* __restrict__ wq, const float* __restrict__ wdkv,
    const float* __restrict__ wuk, const float* __restrict__ wuv,
    const float* __restrict__ wo) {
    int i = blockIdx.x * 256 + threadIdx.x;
    if (i >= NW_TOTAL) return;
    if (i < NWQ) { g_wq_h[i] = __float2half_rn(wq[i]); return; }
    i -= NWQ;
    if (i < NWDKV) { g_wdkv_h[i] = __float2half_rn(wdkv[i]); return; }
    i -= NWDKV;
    if (i < NWUK) { g_wuk_h[i] = __float2half_rn(wuk[i]); return; }
    i -= NWUK;
    if (i < NWUV) { g_wuv_h[i] = __float2half_rn(wuv[i]); return; }
    i -= NWUV;
    g_wo_h[i] = __float2half_rn(wo[i]);
}

// big MoE weights: vectorized float4 -> 4 halves (8B) streaming
#define NW1 (NE*DH*DM)
#define NW2 (NE*DM*DH)
__global__ __launch_bounds__(256) void cvtw2_kernel(
    const float* __restrict__ w1, const float* __restrict__ w2) {
    long n1 = NW1 / 4, n2 = NW2 / 4;
    long i = (long)blockIdx.x * 256 + threadIdx.x;
    long stride = (long)gridDim.x * 256;
    for (; i < n1 + n2; i += stride) {
        float4 v;
        if (i < n1) v = ((const float4*)w1)[i];
        else        v = ((const float4*)w2)[i - n1];
        __half2 lo = __floats2half2_rn(v.x, v.y);
        __half2 hi = __floats2half2_rn(v.z, v.w);
        uint2 o;
        o.x = *(unsigned*)&lo; o.y = *(unsigned*)&hi;
        if (i < n1) ((uint2*)g_w1_h)[i] = o;
        else        ((uint2*)g_w2_h)[i - n1] = o;
    }
}

// ---------------- elementwise ----------------
__global__ __launch_bounds__(256) void rmsnorm_h_kernel(
    const float* __restrict__ x, const float* __restrict__ w, __half* __restrict__ out) {
    int row = blockIdx.x, tid = threadIdx.x;
    const float* xr = x + (long)row * DM;
    float ss = 0.f;
    for (int d = tid; d < DM; d += 256) { float v = xr[d]; ss += v * v; }
    __shared__ float red[256];
    red[tid] = ss; __syncthreads();
    for (int s = 128; s > 0; s >>= 1) { if (tid < s) red[tid] += red[tid + s]; __syncthreads(); }
    float scale = rsqrtf(red[0] / DM + 1e-6f);
    for (int d = tid; d < DM; d += 256) out[(long)row * DM + d] = __float2half_rn(w[d] * xr[d] * scale);
}

// rmsnorm -> fp32 (tf32-rounded, for gate) AND half (for fp16 MoE GEMM)
__global__ __launch_bounds__(256) void rmsnorm_fh_kernel(
    const float* __restrict__ x, const float* __restrict__ w,
    float* __restrict__ outf, __half* __restrict__ outh) {
    int row = blockIdx.x, tid = threadIdx.x;
    const float* xr = x + (long)row * DM;
    float ss = 0.f;
    for (int d = tid; d < DM; d += 256) { float v = xr[d]; ss += v * v; }
    __shared__ float red[256];
    red[tid] = ss; __syncthreads();
    for (int s = 128; s > 0; s >>= 1) { if (tid < s) red[tid] += red[tid + s]; __syncthreads(); }
    float scale = rsqrtf(red[0] / DM + 1e-6f);
    for (int d = tid; d < DM; d += 256) {
        float v = w[d] * xr[d] * scale;
        outf[(long)row * DM + d] = tfr(v);
        outh[(long)row * DM + d] = __float2half_rn(v);
    }
}

__global__ __launch_bounds__(256) void layernorm_h_kernel(
    const float* __restrict__ p, const float* __restrict__ g, const float* __restrict__ b,
    __half* __restrict__ out) {
    int row = blockIdx.x, tid = threadIdx.x;
    const float* xr = p + (long)row * KVL;
    __shared__ float red[256];
    float s = 0.f;
    for (int d = tid; d < KVL; d += 256) s += xr[d];
    red[tid] = s; __syncthreads();
    for (int k = 128; k > 0; k >>= 1) { if (tid < k) red[tid] += red[tid + k]; __syncthreads(); }
    float mu = red[0] / KVL;
    __syncthreads();
    float vs = 0.f;
    for (int d = tid; d < KVL; d += 256) { float dv = xr[d] - mu; vs += dv * dv; }
    red[tid] = vs; __syncthreads();
    for (int k = 128; k > 0; k >>= 1) { if (tid < k) red[tid] += red[tid + k]; __syncthreads(); }
    float inv = rsqrtf(red[0] / KVL + 1e-5f);
    for (int d = tid; d < KVL; d += 256)
        out[(long)row * KVL + d] = __float2half_rn((xr[d] - mu) * inv * g[d] + b[d]);
}

__global__ __launch_bounds__(256) void rope_kernel(float* __restrict__ q, float* __restrict__ k) {
    float* p = blockIdx.y ? k : q;
    int id = blockIdx.x * 256 + threadIdx.x;
    int row = id >> 9;
    int rem = id & 511;
    int h = rem >> 5, d = rem & 31;
    int t = row & (Tdim - 1);
    float* base = p + (long)row * DM + h * HD + d;
    float x1 = base[0], x2 = base[32];
    float inv = powf(10000.f, -(float)d / 32.f);
    float ang = (float)t * inv;
    float sn = sinf(ang), cs = cosf(ang);
    base[0]  = tfr(x1 * cs - x2 * sn);
    base[32] = tfr(x1 * sn + x2 * cs);
}

__global__ void zero_cnt_kernel() { if (threadIdx.x < NE) g_cnt[threadIdx.x] = 0; }

__global__ __launch_bounds__(128) void gate_kernel(
    const float* __restrict__ xn2, const float* __restrict__ gw, const float* __restrict__ gb) {
    int row = blockIdx.x, tid = threadIdx.x;
    const float* xr = xn2 + (long)row * DM;
    float a0 = 0.f, a1 = 0.f, a2 = 0.f, a3 = 0.f;
    for (int d = tid; d < DM; d += 128) {
        float xv = xr[d];
        a0 += xv * gw[d]; a1 += xv * gw[DM + d]; a2 += xv * gw[2 * DM + d]; a3 += xv * gw[3 * DM + d];
    }
    __shared__ float red[4][128];
    red[0][tid] = a0; red[1][tid] = a1; red[2][tid] = a2; red[3][tid] = a3;
    __syncthreads();
    for (int s = 64; s > 0; s >>= 1) {
        if (tid < s) { for (int e = 0; e < 4; e++) red[e][tid] += red[e][tid + s]; }
        __syncthreads();
    }
    if (tid == 0) {
        float l0 = red[0][0] + gb[0], l1 = red[1][0] + gb[1];
        float l2 = red[2][0] + gb[2], l3 = red[3][0] + gb[3];
        int best = 0; float bv = l0;
        if (l1 > bv) { bv = l1; best = 1; }
        if (l2 > bv) { bv = l2; best = 2; }
        if (l3 > bv) { bv = l3; best = 3; }
        int pos = atomicAdd(&g_cnt[best], 1);
        g_idx[best * BT + pos] = row;
    }
}

// ---------------- fp16 mma GEMM (all GEMMs) ----------------
// C[M,N] = A[M,K] * B[N,K]^T, A/B half, acc fp32. Block 128x128x32, 512 threads,
// 16 warps (4x4), warp tile 32x32, mma m16n8k16, 2-stage cp.async.
// Optional: expert stride (blockIdx.z), row gather, bias, relu, fp32 residual,
// half or fp32 output (Ch != nullptr -> half).
#define FLDH 40
#define FSTG (2 * 128 * FLDH)
#define F16_SMEM (2 * FSTG * 2)

__global__ __launch_bounds__(512) void gemm_f16(
    const __half* __restrict__ A, const __half* __restrict__ Bw,
    float* __restrict__ Cf, __half* __restrict__ Ch,
    int M, int N, int K,
    const float* __restrict__ bias, const float* __restrict__ res,
    int relu, int use_idx, long wstride, int cvt_out) {
    extern __shared__ __half hsm[];
    unsigned sbase = (unsigned)__cvta_generic_to_shared(hsm);

    int e = blockIdx.z;
    const __half* Bm = Bw + (long)e * wstride;
    int Mz = M;
    const int* rowmap = nullptr;
    if (use_idx) { Mz = g_cnt[e]; rowmap = g_idx + e * BT; }
    int i0 = blockIdx.y * 128;
    if (i0 >= Mz) return;
    int j0 = blockIdx.x * 128;

    int tid = threadIdx.x;
    int warp = tid >> 5, lane = tid & 31;
    int wm = warp >> 2, wn = warp & 3;
    int lg = lane >> 2, lr = lane & 3;

    int lrow = tid >> 2, lc = tid & 3;
    int apos = i0 + lrow;
    bool av = apos < Mz;
    int asz = av ? 16 : 0;
    int arow = rowmap ? (av ? rowmap[apos] : 0) : apos;

    float acc[2][4][4];
#pragma unroll
    for (int mi = 0; mi < 2; mi++)
#pragma unroll
        for (int ni = 0; ni < 4; ni++)
#pragma unroll
            for (int q = 0; q < 4; q++) acc[mi][ni][q] = 0.f;

    int KT = K / 32;

    {
        unsigned adst = sbase;
        unsigned bdst = sbase + 128 * FLDH * 2;
        cp_async16(adst + (lrow * FLDH + lc * 8) * 2, A + (long)arow * K + lc * 8, asz);
        cp_async16(bdst + (lrow * FLDH + lc * 8) * 2, Bm + (long)(j0 + lrow) * K + lc * 8, 16);
        cp_commit();
    }

    for (int kt = 0; kt < KT; kt++) {
        cp_wait0();
        __syncthreads();
        if (kt + 1 < KT) {
            int nb = (kt + 1) & 1;
            int k0 = (kt + 1) * 32;
            unsigned adst = sbase + nb * FSTG * 2;
            unsigned bdst = adst + 128 * FLDH * 2;
            cp_async16(adst + (lrow * FLDH + lc * 8) * 2, A + (long)arow * K + k0 + lc * 8, asz);
            cp_async16(bdst + (lrow * FLDH + lc * 8) * 2, Bm + (long)(j0 + lrow) * K + k0 + lc * 8, 16);
            cp_commit();
        }
        const __half* Ah = hsm + (kt & 1) * FSTG;
        const __half* Bh = Ah + 128 * FLDH;
#pragma unroll
        for (int kk = 0; kk < 2; kk++) {
            unsigned af[2][4], bf[4][2];
#pragma unroll
            for (int mi = 0; mi < 2; mi++) {
                int r0 = wm * 32 + mi * 16 + lg;
                af[mi][0] = *(const unsigned*)&Ah[r0 * FLDH + kk * 16 + lr * 2];
                af[mi][1] = *(const unsigned*)&Ah[(r0 + 8) * FLDH + kk * 16 + lr * 2];
                af[mi][2] = *(const unsigned*)&Ah[r0 * FLDH + kk * 16 + 8 + lr * 2];
                af[mi][3] = *(const unsigned*)&Ah[(r0 + 8) * FLDH + kk * 16 + 8 + lr * 2];
            }
#pragma unroll
            for (int ni = 0; ni < 4; ni++) {
                int c0 = wn * 32 + ni * 8 + lg;
                bf[ni][0] = *(const unsigned*)&Bh[c0 * FLDH + kk * 16 + lr * 2];
                bf[ni][1] = *(const unsigned*)&Bh[c0 * FLDH + kk * 16 + 8 + lr * 2];
            }
#pragma unroll
            for (int mi = 0; mi < 2; mi++)
#pragma unroll
                for (int ni = 0; ni < 4; ni++)
                    mma_f16(acc[mi][ni], af[mi], bf[ni][0], bf[ni][1]);
        }
    }

    // epilogue
#pragma unroll
    for (int mi = 0; mi < 2; mi++) {
        int pos0 = i0 + wm * 32 + mi * 16 + lg;
        int pos1 = pos0 + 8;
        bool v0 = pos0 < Mz, v1 = pos1 < Mz;
        int cr0 = v0 ? (rowmap ? rowmap[pos0] : pos0) : 0;
        int cr1 = v1 ? (rowmap ? rowmap[pos1] : pos1) : 0;
#pragma unroll
        for (int ni = 0; ni < 4; ni++) {
            int col = j0 + wn * 32 + ni * 8 + lr * 2;
            float b0v = 0.f, b1v = 0.f;
            if (bias) { b0v = bias[(long)e * N + col]; b1v = bias[(long)e * N + col + 1]; }
            if (v0) {
                float x0 = acc[mi][ni][0] + b0v, x1 = acc[mi][ni][1] + b1v;
                if (relu) { x0 = fmaxf(x0, 0.f); x1 = fmaxf(x1, 0.f); }
                if (res) { x0 += res[(long)cr0 * N + col]; x1 += res[(long)cr0 * N + col + 1]; }
                if (Ch) {
                    *(__half2*)&Ch[(long)cr0 * N + col] = __floats2half2_rn(x0, x1);
                } else {
                    if (cvt_out) { x0 = tfr(x0); x1 = tfr(x1); }
                    *(float2*)&Cf[(long)cr0 * N + col] = make_float2(x0, x1);
                }
            }
            if (v1) {
                float x0 = acc[mi][ni][2] + b0v, x1 = acc[mi][ni][3] + b1v;
                if (relu) { x0 = fmaxf(x0, 0.f); x1 = fmaxf(x1, 0.f); }
                if (res) { x0 += res[(long)cr1 * N + col]; x1 += res[(long)cr1 * N + col + 1]; }
                if (Ch) {
                    *(__half2*)&Ch[(long)cr1 * N + col] = __floats2half2_rn(x0, x1);
                } else {
                    if (cvt_out) { x0 = tfr(x0); x1 = tfr(x1); }
                    *(float2*)&Cf[(long)cr1 * N + col] = make_float2(x0, x1);
                }
            }
        }
    }
}

// ---------------- fused flash attention (tf32 mma; output half for Wo GEMM) ------
#define FA_LD 68
#define FA_SMEM (3 * 64 * FA_LD * 4)

__global__ __launch_bounds__(128) void flash_attn_kernel(
    const float* __restrict__ Q, const float* __restrict__ Kg,
    const float* __restrict__ Vg, __half* __restrict__ O) {
    extern __shared__ float sm[];
    float* Ks = sm;
    float* Vs = sm + 64 * FA_LD;
    float* Ps = sm + 2 * 64 * FA_LD;

    int qt = blockIdx.x;
    int z  = blockIdx.y;
    int b  = z >> 4, h = z & 15;
    int q0 = qt * 64;
    int tid = threadIdx.x, warp = tid >> 5, lane = tid & 31;
    int lg = lane >> 2, lr = lane & 3;

    const float* Qb = Q  + (long)(b * Tdim) * DM + h * HD;
    const float* Kb = Kg + (long)(b * Tdim) * DM + h * HD;
    const float* Vb = Vg + (long)(b * Tdim) * DM + h * HD;

    for (int it = tid; it < 64 * 16; it += 128) {
        int r = it >> 4, c4 = it & 15;
        *(float4*)&Ps[r * FA_LD + c4 * 4] = *(const float4*)(Qb + (long)(q0 + r) * DM + c4 * 4);
    }
    __syncthreads();
    unsigned qa[8][4];
    int rlo = warp * 16 + lg;
#pragma unroll
    for (int ks = 0; ks < 8; ks++) {
        qa[ks][0] = __float_as_uint(Ps[(rlo)     * FA_LD + ks * 8 + lr]);
        qa[ks][1] = __float_as_uint(Ps[(rlo + 8) * FA_LD + ks * 8 + lr]);
        qa[ks][2] = __float_as_uint(Ps[(rlo)     * FA_LD + ks * 8 + lr + 4]);
        qa[ks][3] = __float_as_uint(Ps[(rlo + 8) * FA_LD + ks * 8 + lr + 4]);
    }

    float o[8][4];
#pragma unroll
    for (int nf = 0; nf < 8; nf++)
#pragma unroll
        for (int e = 0; e < 4; e++) o[nf][e] = 0.f;
    float m_lo = -1e30f, m_hi = -1e30f, l_lo = 0.f, l_hi = 0.f;

    int row_lo = q0 + warp * 16 + lg;
    int row_hi = row_lo + 8;

    for (int kc = 0; kc <= qt; kc++) {
        __syncthreads();
        for (int it = tid; it < 64 * 16; it += 128) {
            int r = it >> 4, c4 = it & 15;
            *(float4*)&Ks[r * FA_LD + c4 * 4] = *(const float4*)(Kb + (long)(kc * 64 + r) * DM + c4 * 4);
            *(float4*)&Vs[r * FA_LD + c4 * 4] = *(const float4*)(Vb + (long)(kc * 64 + r) * DM + c4 * 4);
        }
        __syncthreads();

        float s[8][4];
#pragma unroll
        for (int nf = 0; nf < 8; nf++)
#pragma unroll
            for (int e = 0; e < 4; e++) s[nf][e] = 0.f;
#pragma unroll
        for (int ks = 0; ks < 8; ks++) {
#pragma unroll
            for (int nf = 0; nf < 8; nf++) {
                unsigned b0 = __float_as_uint(Ks[(nf * 8 + lg) * FA_LD + ks * 8 + lr]);
                unsigned b1 = __float_as_uint(Ks[(nf * 8 + lg) * FA_LD + ks * 8 + lr + 4]);
                mma_tf32(s[nf], qa[ks], b0, b1);
            }
        }

        int colbase = kc * 64 + lr * 2;
#pragma unroll
        for (int nf = 0; nf < 8; nf++) {
            int c0 = colbase + nf * 8;
            s[nf][0] = (c0     <= row_lo) ? s[nf][0] * 0.125f : -1e30f;
            s[nf][1] = (c0 + 1 <= row_lo) ? s[nf][1] * 0.125f : -1e30f;
            s[nf][2] = (c0     <= row_hi) ? s[nf][2] * 0.125f : -1e30f;
            s[nf][3] = (c0 + 1 <= row_hi) ? s[nf][3] * 0.125f : -1e30f;
        }

        float cm_lo = -1e30f, cm_hi = -1e30f;
#pragma unroll
        for (int nf = 0; nf < 8; nf++) {
            cm_lo = fmaxf(cm_lo, fmaxf(s[nf][0], s[nf][1]));
            cm_hi = fmaxf(cm_hi, fmaxf(s[nf][2], s[nf][3]));
        }
        cm_lo = fmaxf(cm_lo, __shfl_xor_sync(0xffffffffu, cm_lo, 1));
        cm_lo = fmaxf(cm_lo, __shfl_xor_sync(0xffffffffu, cm_lo, 2));
        cm_hi = fmaxf(cm_hi, __shfl_xor_sync(0xffffffffu, cm_hi, 1));
        cm_hi = fmaxf(cm_hi, __shfl_xor_sync(0xffffffffu, cm_hi, 2));

        float nm_lo = fmaxf(m_lo, cm_lo), nm_hi = fmaxf(m_hi, cm_hi);
        float al_lo = __expf(m_lo - nm_lo), al_hi = __expf(m_hi - nm_hi);
        m_lo = nm_lo; m_hi = nm_hi;

        float ps_lo = 0.f, ps_hi = 0.f;
#pragma unroll
        for (int nf = 0; nf < 8; nf++) {
            s[nf][0] = __expf(s[nf][0] - m_lo);
            s[nf][1] = __expf(s[nf][1] - m_lo);
            s[nf][2] = __expf(s[nf][2] - m_hi);
            s[nf][3] = __expf(s[nf][3] - m_hi);
            ps_lo += s[nf][0] + s[nf][1];
            ps_hi += s[nf][2] + s[nf][3];
        }
        ps_lo += __shfl_xor_sync(0xffffffffu, ps_lo, 1);
        ps_lo += __shfl_xor_sync(0xffffffffu, ps_lo, 2);
        ps_hi += __shfl_xor_sync(0xffffffffu, ps_hi, 1);
        ps_hi += __shfl_xor_sync(0xffffffffu, ps_hi, 2);
        l_lo = l_lo * al_lo + ps_lo;
        l_hi = l_hi * al_hi + ps_hi;

#pragma unroll
        for (int nf = 0; nf < 8; nf++) {
            o[nf][0] *= al_lo; o[nf][1] *= al_lo;
            o[nf][2] *= al_hi; o[nf][3] *= al_hi;
        }

        int prl = warp * 16 + lg;
#pragma unroll
        for (int nf = 0; nf < 8; nf++) {
            Ps[(prl)     * FA_LD + nf * 8 + lr * 2]     = tfr(s[nf][0]);
            Ps[(prl)     * FA_LD + nf * 8 + lr * 2 + 1] = tfr(s[nf][1]);
            Ps[(prl + 8) * FA_LD + nf * 8 + lr * 2]     = tfr(s[nf][2]);
            Ps[(prl + 8) * FA_LD + nf * 8 + lr * 2 + 1] = tfr(s[nf][3]);
        }
        __syncwarp();

#pragma unroll
        for (int ks = 0; ks < 8; ks++) {
            unsigned pa[4];
            pa[0] = __float_as_uint(Ps[(prl)     * FA_LD + ks * 8 + lr]);
            pa[1] = __float_as_uint(Ps[(prl + 8) * FA_LD + ks * 8 + lr]);
            pa[2] = __float_as_uint(Ps[(prl)     * FA_LD + ks * 8 + lr + 4]);
            pa[3] = __float_as_uint(Ps[(prl + 8) * FA_LD + ks * 8 + lr + 4]);
#pragma unroll
            for (int nf = 0; nf < 8; nf++) {
                unsigned b0 = __float_as_uint(Vs[(ks * 8 + lr)     * FA_LD + nf * 8 + lg]);
                unsigned b1 = __float_as_uint(Vs[(ks * 8 + lr + 4) * FA_LD + nf * 8 + lg]);
                mma_tf32(o[nf], pa, b0, b1);
            }
        }
    }

    float inv_lo = 1.f / l_lo, inv_hi = 1.f / l_hi;
    long out_lo = (long)(b * Tdim + row_lo) * DM + h * HD;
    long out_hi = (long)(b * Tdim + row_hi) * DM + h * HD;
#pragma unroll
    for (int nf = 0; nf < 8; nf++) {
        int c = nf * 8 + lr * 2;
        __half2 vlo = __floats2half2_rn(o[nf][0] * inv_lo, o[nf][1] * inv_lo);
        __half2 vhi = __floats2half2_rn(o[nf][2] * inv_hi, o[nf][3] * inv_hi);
        *(__half2*)&O[out_lo + c] = vlo;
        *(__half2*)&O[out_hi + c] = vhi;
    }
}

// ---------------- launch ----------------
extern "C" void kernel_launch(void* const* d_in, const int* in_sizes, int n_in,
                              void* d_out, int out_size) {
    const float* x       = (const float*)d_in[0];
    const float* norm1_w = (const float*)d_in[1];
    const float* norm2_w = (const float*)d_in[2];
    const float* Wq      = (const float*)d_in[3];
    const float* Wdkv    = (const float*)d_in[4];
    const float* Wuk     = (const float*)d_in[5];
    const float* Wuv     = (const float*)d_in[6];
    const float* Wo      = (const float*)d_in[7];
    const float* ln_g    = (const float*)d_in[8];
    const float* ln_b    = (const float*)d_in[9];
    const float* gate_w  = (const float*)d_in[10];
    const float* gate_b  = (const float*)d_in[11];
    const float* W1      = (const float*)d_in[12];
    const float* b1      = (const float*)d_in[13];
    const float* W2      = (const float*)d_in[14];
    const float* b2      = (const float*)d_in[15];
    float* out = (float*)d_out;

    __half *p_xn_h, *p_lat_h, *p_attn_h, *p_xn2_h, *p_h_h;
    __half *p_wq_h, *p_wdkv_h, *p_wuk_h, *p_wuv_h, *p_wo_h, *p_w1_h, *p_w2_h;
    float *p_q, *p_lat, *p_k, *p_v, *p_x1, *p_xn2;
    cudaGetSymbolAddress((void**)&p_xn_h,  g_xn_h);
    cudaGetSymbolAddress((void**)&p_q,     g_q);
    cudaGetSymbolAddress((void**)&p_lat,   g_lat);
    cudaGetSymbolAddress((void**)&p_lat_h, g_lat_h);
    cudaGetSymbolAddress((void**)&p_k,     g_k);
    cudaGetSymbolAddress((void**)&p_v,     g_v);
    cudaGetSymbolAddress((void**)&p_attn_h,g_attn_h);
    cudaGetSymbolAddress((void**)&p_x1,    g_x1);
    cudaGetSymbolAddress((void**)&p_xn2,   g_xn2);
    cudaGetSymbolAddress((void**)&p_xn2_h, g_xn2_h);
    cudaGetSymbolAddress((void**)&p_h_h,   g_h_h);
    cudaGetSymbolAddress((void**)&p_wq_h,  g_wq_h);
    cudaGetSymbolAddress((void**)&p_wdkv_h,g_wdkv_h);
    cudaGetSymbolAddress((void**)&p_wuk_h, g_wuk_h);
    cudaGetSymbolAddress((void**)&p_wuv_h, g_wuv_h);
    cudaGetSymbolAddress((void**)&p_wo_h,  g_wo_h);
    cudaGetSymbolAddress((void**)&p_w1_h,  g_w1_h);
    cudaGetSymbolAddress((void**)&p_w2_h,  g_w2_h);

    cudaFuncSetAttribute(flash_attn_kernel, cudaFuncAttributeMaxDynamicSharedMemorySize, FA_SMEM);
    cudaFuncSetAttribute(gemm_f16, cudaFuncAttributeMaxDynamicSharedMemorySize, F16_SMEM);

    // 0. weight conversions (small: 14MB; big MoE: 128MB read / 64MB write, streaming)
    cvtw5_kernel<<<(NW_TOTAL + 255) / 256, 256>>>(Wq, Wdkv, Wuk, Wuv, Wo);
    cvtw2_kernel<<<16384, 256>>>(W1, W2);

    // 1. xn = rmsnorm(x)  [half]
    rmsnorm_h_kernel<<<BT, 256>>>(x, norm1_w, p_xn_h);
    // 2. q = xn @ Wq^T  [fp16 gemm -> fp32]
    gemm_f16<<<dim3(DM/128, BT/128), 512, F16_SMEM>>>(p_xn_h, p_wq_h, p_q, nullptr, BT, DM, DM, nullptr, nullptr, 0, 0, 0, 0);
    // 3. lat = layernorm(xn @ Wdkv^T)  [fp16 gemm -> fp32 -> half]
    gemm_f16<<<dim3(KVL/128, BT/128), 512, F16_SMEM>>>(p_xn_h, p_wdkv_h, p_lat, nullptr, BT, KVL, DM, nullptr, nullptr, 0, 0, 0, 0);
    layernorm_h_kernel<<<BT, 256>>>(p_lat, ln_g, ln_b, p_lat_h);
    // 4. k, v  [fp16 gemms; v tf32-rounded for flash]
    gemm_f16<<<dim3(DM/128, BT/128), 512, F16_SMEM>>>(p_lat_h, p_wuk_h, p_k, nullptr, BT, DM, KVL, nullptr, nullptr, 0, 0, 0, 0);
    gemm_f16<<<dim3(DM/128, BT/128), 512, F16_SMEM>>>(p_lat_h, p_wuv_h, p_v, nullptr, BT, DM, KVL, nullptr, nullptr, 0, 0, 0, 1);
    // 5. RoPE on q and k  [tf32-rounded fp32]
    rope_kernel<<<dim3(4096, 2), 256>>>(p_q, p_k);
    // 6. fused flash attention  [out: half]
    flash_attn_kernel<<<dim3(Tdim/64, 32), 128, FA_SMEM>>>(p_q, p_k, p_v, p_attn_h);
    // 7. x1 = x + attn @ Wo^T  [fp16 gemm + fp32 residual]
    gemm_f16<<<dim3(DM/128, BT/128), 512, F16_SMEM>>>(p_attn_h, p_wo_h, p_x1, nullptr, BT, DM, DM, nullptr, x, 0, 0, 0, 0);
    // 8. xn2 = rmsnorm(x1)  [fp32 tf32-rounded for gate + half for MoE]
    rmsnorm_fh_kernel<<<BT, 256>>>(p_x1, norm2_w, p_xn2, p_xn2_h);
    // 9. gating (fp32, routing identical to champion)
    zero_cnt_kernel<<<1, 32>>>();
    gate_kernel<<<BT, 128>>>(p_xn2, gate_w, gate_b);
    // 10. MoE expert GEMMs  [fp16; h in half]
    gemm_f16<<<dim3(DH/128, BT/128, NE), 512, F16_SMEM>>>(
        p_xn2_h, p_w1_h, nullptr, p_h_h, BT, DH, DM, b1, nullptr, 1, 1, (long)DH * DM, 0);
    gemm_f16<<<dim3(DM/128, BT/128, NE), 512, F16_SMEM>>>(
        p_h_h, p_w2_h, out, nullptr, BT, DM, DH, b2, p_x1, 0, 1, (long)DM * DH, 0);
    (void)in_sizes; (void)n_in; (void)out_size;
}